// round 15
// baseline (speedup 1.0000x reference)
#include <cuda_runtime.h>
#include <math.h>

#define BB 4
#define DD 256
#define NN 2048
#define HH 4
#define HDIM 64
#define TS 64          // attention tile
#define TP 68          // padded row length

typedef unsigned long long u64;

// ---------------- packed f32x2 helpers (sm_103a) ----------------
__device__ __forceinline__ u64 pk2(float x, float y) {
    u64 r; asm("mov.b64 %0, {%1, %2};" : "=l"(r) : "f"(x), "f"(y)); return r;
}
__device__ __forceinline__ void upk2(u64 p, float& x, float& y) {
    asm("mov.b64 {%0, %1}, %2;" : "=f"(x), "=f"(y) : "l"(p));
}
__device__ __forceinline__ void fma2(u64& d, u64 a, u64 b) {
    asm("fma.rn.f32x2 %0, %1, %2, %0;" : "+l"(d) : "l"(a), "l"(b));
}
__device__ __forceinline__ u64 mul2(u64 a, u64 b) {
    u64 d; asm("mul.rn.f32x2 %0, %1, %2;" : "=l"(d) : "l"(a), "l"(b)); return d;
}

// ---------------- scratch (no allocations allowed) ----------------
__device__ float g_q[BB*DD*NN];
__device__ float g_k[BB*DD*NN];
__device__ float g_v[BB*DD*NN];
__device__ float g_msg[BB*DD*NN];
__device__ float g_h2[BB*2*DD*NN];
__device__ float g_wfull[2*DD*2*DD];   // [512][512]: [W1x | W1m@Wm]
__device__ float g_bc[2*DD];           // b1 + W1m@bm

// ---------------- GEMM body: 128x128 tile, 8x8 microtile, f32x2 FMA, prefetch ----------------
// C = relu?(A @ [B0; B1] + bias) for the (blockIdx.y, blockIdx.x) 128x128 tile.
__device__ __forceinline__
void gemm_body(const float* __restrict__ A,
               const float* __restrict__ B0, const float* __restrict__ B1,
               float* __restrict__ C, const float* __restrict__ bias,
               int K, int Ksplit, int lda, int ldb, int ldc, int relu)
{
    __shared__ float As[16][132];
    __shared__ float Bs[16][132];

    const int iBase = blockIdx.y * 128;
    const int jBase = blockIdx.x * 128;
    const int tid = threadIdx.x;
    const int i0 = (tid & 15) * 4;    // rows: i0..i0+3 and i0+64..i0+67
    const int j0 = (tid >> 4) * 4;    // cols: j0..j0+3 and j0+64..j0+67

    const int aK4 = tid & 3,  aI = tid >> 2;   // A: k = 4*aK4.., i = aI + rep*64
    const int bJ4 = tid & 31, bK = tid >> 5;   // B: j = 4*bJ4.., k = bK + rep*8

    u64 acc2[8][4];                    // [row][col-pair] packed fp32 pairs
#pragma unroll
    for (int r = 0; r < 8; r++)
#pragma unroll
        for (int c = 0; c < 4; c++) acc2[r][c] = 0ULL;

    float4 ra[2], rb[2];

    // ---- prologue: load tile kt=0 (LDG.128)
    {
#pragma unroll
        for (int rep = 0; rep < 2; rep++)
            ra[rep] = *(const float4*)&A[(long long)(iBase + aI + rep * 64) * lda + 4 * aK4];
#pragma unroll
        for (int rep = 0; rep < 2; rep++) {
            int krow = bK + rep * 8;
            const float* src = (krow < Ksplit)
                ? (B0 + (long long)krow * ldb)
                : (B1 + (long long)(krow - Ksplit) * ldb);
            rb[rep] = *(const float4*)&src[jBase + 4 * bJ4];
        }
    }

    for (int kt = 0; kt < K; kt += 16) {
        // ---- commit staged tile to smem
#pragma unroll
        for (int rep = 0; rep < 2; rep++) {
            As[4 * aK4 + 0][aI + rep * 64] = ra[rep].x;
            As[4 * aK4 + 1][aI + rep * 64] = ra[rep].y;
            As[4 * aK4 + 2][aI + rep * 64] = ra[rep].z;
            As[4 * aK4 + 3][aI + rep * 64] = ra[rep].w;
        }
#pragma unroll
        for (int rep = 0; rep < 2; rep++)
            *(float4*)&Bs[bK + rep * 8][4 * bJ4] = rb[rep];
        __syncthreads();

        // ---- prefetch next tile (LDG latency hidden by FMA block below)
        if (kt + 16 < K) {
            const int ktn = kt + 16;
#pragma unroll
            for (int rep = 0; rep < 2; rep++)
                ra[rep] = *(const float4*)&A[(long long)(iBase + aI + rep * 64) * lda + ktn + 4 * aK4];
#pragma unroll
            for (int rep = 0; rep < 2; rep++) {
                int krow = ktn + bK + rep * 8;
                const float* src = (krow < Ksplit)
                    ? (B0 + (long long)krow * ldb)
                    : (B1 + (long long)(krow - Ksplit) * ldb);
                rb[rep] = *(const float4*)&src[jBase + 4 * bJ4];
            }
        }

        // ---- compute: per kk, 4 LDS.128 + 8 pack + 32 FFMA2 (= 64 FMA)
#pragma unroll
        for (int kk = 0; kk < 16; kk++) {
            float4 a0 = *(const float4*)&As[kk][i0];
            float4 a1 = *(const float4*)&As[kk][i0 + 64];
            ulonglong2 b0p = *(const ulonglong2*)&Bs[kk][j0];
            ulonglong2 b1p = *(const ulonglong2*)&Bs[kk][j0 + 64];
            const float arr[8] = {a0.x, a0.y, a0.z, a0.w, a1.x, a1.y, a1.z, a1.w};
#pragma unroll
            for (int r = 0; r < 8; r++) {
                u64 ap = pk2(arr[r], arr[r]);
                fma2(acc2[r][0], ap, b0p.x);
                fma2(acc2[r][1], ap, b0p.y);
                fma2(acc2[r][2], ap, b1p.x);
                fma2(acc2[r][3], ap, b1p.y);
            }
        }
        __syncthreads();
    }

    // epilogue: unpack, bias + optional relu, float4 stores
#pragma unroll
    for (int ih = 0; ih < 2; ih++) {
#pragma unroll
        for (int r = 0; r < 4; r++) {
            int gi = iBase + i0 + ih * 64 + r;
            float bv = bias ? bias[gi] : 0.f;
            int rr = ih * 4 + r;
#pragma unroll
            for (int jh = 0; jh < 2; jh++) {
                int gj = jBase + j0 + jh * 64;
                float4 o;
                upk2(acc2[rr][jh * 2 + 0], o.x, o.y);
                upk2(acc2[rr][jh * 2 + 1], o.z, o.w);
                o.x += bv; o.y += bv; o.z += bv; o.w += bv;
                if (relu) {
                    o.x = fmaxf(o.x, 0.f); o.y = fmaxf(o.y, 0.f);
                    o.z = fmaxf(o.z, 0.f); o.w = fmaxf(o.w, 0.f);
                }
                *(float4*)&C[(long long)gi * ldc + gj] = o;
            }
        }
    }
}

// generic batched entry (batch in blockIdx.z), ld = NN for B and C
__global__ __launch_bounds__(256, 2)
void gemm128_k(const float* __restrict__ A,
               const float* __restrict__ B0, const float* __restrict__ B1,
               float* __restrict__ C, const float* __restrict__ bias,
               int K, int Ksplit, int lda, int relu)
{
    const int M = gridDim.y * 128;
    const long long bz = blockIdx.z;
    gemm_body(A,
              B0 + bz * (long long)Ksplit * NN,
              B1 + bz * (long long)(K - Ksplit) * NN,
              C  + bz * (long long)M * NN,
              bias, K, Ksplit, lda, NN, NN, relu);
}

// fused Q/K/V projections: blockIdx.z = w*4 + batch, w in {0,1,2}
__global__ __launch_bounds__(256, 2)
void qkv_k(const float* __restrict__ Wq, const float* __restrict__ Wk,
           const float* __restrict__ Wv,
           const float* __restrict__ bq, const float* __restrict__ bk,
           const float* __restrict__ bv,
           const float* __restrict__ x, const float* __restrict__ source,
           float* __restrict__ q, float* __restrict__ k, float* __restrict__ v)
{
    const int w  = blockIdx.z >> 2;
    const int bz = blockIdx.z & 3;
    const float* A    = (w == 0) ? Wq : (w == 1) ? Wk : Wv;
    const float* bias = (w == 0) ? bq : (w == 1) ? bk : bv;
    const float* B    = (w == 0) ? x : source;
    float*       C    = (w == 0) ? q : (w == 1) ? k : v;
    const long long off = (long long)bz * DD * NN;
    gemm_body(A, B + off, B + off, C + off, bias, DD, DD, DD, NN, NN, 0);
}

// weight-fold GEMM: Wfull[:,256:512] = W1[:,256:512] @ Wm
__global__ __launch_bounds__(256, 2)
void fold_ww_k(const float* __restrict__ W1, const float* __restrict__ Wm,
               float* __restrict__ Wfull)
{
    gemm_body(W1 + DD, Wm, Wm, Wfull + DD, nullptr,
              DD, DD, 2 * DD, DD, 2 * DD, 0);
}

// copy left half: Wfull[:,0:256] = W1[:,0:256]
__global__ __launch_bounds__(256)
void fold_copy_k(const float* __restrict__ W1, float* __restrict__ Wfull)
{
    int idx = blockIdx.x * 256 + threadIdx.x;     // < 512*256
    int i = idx >> 8, k = idx & (DD - 1);
    Wfull[(long long)i * 2 * DD + k] = W1[(long long)i * 2 * DD + k];
}

// folded bias: bc = b1 + W1[:,256:512] @ bm
__global__ __launch_bounds__(256)
void fold_bias_k(const float* __restrict__ W1, const float* __restrict__ bm,
                 const float* __restrict__ b1, float* __restrict__ bc)
{
    int i = blockIdx.x * 256 + threadIdx.x;       // < 512
    float s = b1[i];
    for (int k = 0; k < DD; k++)
        s += W1[(long long)i * 2 * DD + DD + k] * bm[k];
    bc[i] = s;
}

// ---------------- fused flash attention with edge weighting (f32x2) ----------------
// msg[b,d,h,n] = (sum_m exp(S-M)*edge[b,n,m]*v[b,d,h,m]) / (sum_m exp(S-M))
// Strided row ownership (rows ti+16a). Q stored PRE-DUPLICATED as u64 pairs.
// Softmax phase loads S once (LDS.64), reuses for max+exp, writes P' as STS.64.
__global__ __launch_bounds__(256, 2)
void flash_edge_k(const float* __restrict__ q, const float* __restrict__ k,
                  const float* __restrict__ v, const float* __restrict__ edge,
                  float* __restrict__ msg)
{
    extern __shared__ float smem[];
    u64*   QD = (u64*)smem;            // [TS][TS] u64: (q,q) duplicated; 32 KB.
                                       //   reused as float out-staging [d][TP] at the end
    float* Ks = smem + 2 * TS * TS;    // [TS][TP]  K tile [d][m]; reused as edge tile [r][m]
    float* Vs = Ks + TS * TP;          // [TS][TP]  V tile [d][m]
    float* Ss = Vs + TS * TP;          // [TS][TP]  scores [r][m] -> P in place
    float* Mrow = Ss + TS * TP;        // [TS]
    float* Drow = Mrow + TS;           // [TS]
    float* Sc   = Drow + TS;           // [TS]

    const int z = blockIdx.y;
    const int b = z >> 2, h = z & 3;
    const int nBase = blockIdx.x * TS;
    const long long hd = (long long)HH * NN;
    const float* qp = q + (long long)b * DD * NN + (long long)h * NN;
    const float* kp = k + (long long)b * DD * NN + (long long)h * NN;
    const float* vp = v + (long long)b * DD * NN + (long long)h * NN;
    const float* ep = edge + (long long)b * NN * NN;

    const int tid = threadIdx.x;
    const int ti = tid & 15, tj = tid >> 4;
    const int c0 = tj * 4;                     // owned S cols / output dims
    const int t4 = tid & 15, tHi = tid >> 4;   // float4 transfer coords

    // Q tile: load float4 over r, store duplicated u64 pairs QD[d][r] = (q,q)
#pragma unroll
    for (int rep = 0; rep < 4; rep++) {
        int d = tHi + rep * 16;
        float4 qv4 = *(const float4*)&qp[(long long)d * hd + nBase + 4 * t4];
        ulonglong2 p01, p23;
        p01.x = pk2(qv4.x, qv4.x); p01.y = pk2(qv4.y, qv4.y);
        p23.x = pk2(qv4.z, qv4.z); p23.y = pk2(qv4.w, qv4.w);
        *(ulonglong2*)&QD[d * TS + 4 * t4 + 0] = p01;
        *(ulonglong2*)&QD[d * TS + 4 * t4 + 2] = p23;
    }
    if (tid < TS) { Mrow[tid] = -1e30f; Drow[tid] = 0.f; }

    u64 acc2[4][4];                    // [row a][col c], packed over m-parity
#pragma unroll
    for (int a = 0; a < 4; a++)
#pragma unroll
        for (int c = 0; c < 4; c++) acc2[a][c] = 0ULL;
    __syncthreads();

    for (int mBase = 0; mBase < NN; mBase += TS) {
        // K/V tiles [d][m], float4 over m
#pragma unroll
        for (int rep = 0; rep < 4; rep++) {
            int d = tHi + rep * 16;
            *(float4*)&Ks[d * TP + 4 * t4] =
                *(const float4*)&kp[(long long)d * hd + mBase + 4 * t4];
            *(float4*)&Vs[d * TP + 4 * t4] =
                *(const float4*)&vp[(long long)d * hd + mBase + 4 * t4];
        }
        __syncthreads();

        // ---- issue edge-tile LDG.128s early; latency hidden by the S FMA block
        float4 er[4];
#pragma unroll
        for (int rep = 0; rep < 4; rep++)
            er[rep] = *(const float4*)&ep[(long long)(nBase + tHi + rep * 16) * NN + mBase + 4 * t4];

        // S[r][m], rows ti+16a, col-pairs: per dd 1 LDS.128 + 4 LDS.64 + 8 FFMA2
        u64 s2[4][2];
#pragma unroll
        for (int a = 0; a < 4; a++) { s2[a][0] = 0ULL; s2[a][1] = 0ULL; }
#pragma unroll
        for (int dd = 0; dd < TS; dd++) {
            ulonglong2 kp2 = *(const ulonglong2*)&Ks[dd * TP + c0];
#pragma unroll
            for (int a = 0; a < 4; a++) {
                u64 qq = QD[dd * TS + ti + 16 * a];
                fma2(s2[a][0], qq, kp2.x);
                fma2(s2[a][1], qq, kp2.y);
            }
        }
        __syncthreads();   // done reading Ks (K data)

        // store S (scaled) via STS.64, and commit edge registers into Ks: Es[r][m]
        {
            const u64 kscale = pk2(0.125f, 0.125f);
#pragma unroll
            for (int a = 0; a < 4; a++) {
                *(u64*)&Ss[(ti + 16 * a) * TP + c0 + 0] = mul2(s2[a][0], kscale);
                *(u64*)&Ss[(ti + 16 * a) * TP + c0 + 2] = mul2(s2[a][1], kscale);
            }
        }
#pragma unroll
        for (int rep = 0; rep < 4; rep++)
            *(float4*)&Ks[(tHi + rep * 16) * TP + 4 * t4] = er[rep];
        __syncthreads();

        // online softmax: load S once (LDS.64), reuse for max+exp; P' via STS.64
        {
            const int row = tid >> 2, seg = tid & 3;
            const int base = row * TP + seg * 16;   // even -> 8B aligned
            float sv[16];
#pragma unroll
            for (int jj = 0; jj < 8; jj++) {
                u64 w = *(const u64*)&Ss[base + 2 * jj];
                upk2(w, sv[2 * jj], sv[2 * jj + 1]);
            }
            float mx = -1e30f;
#pragma unroll
            for (int j = 0; j < 16; j++) mx = fmaxf(mx, sv[j]);
            mx = fmaxf(mx, __shfl_xor_sync(0xffffffffu, mx, 1));
            mx = fmaxf(mx, __shfl_xor_sync(0xffffffffu, mx, 2));
            float Mold = Mrow[row];
            float Mnew = fmaxf(Mold, mx);
            float sum = 0.f;
#pragma unroll
            for (int j = 0; j < 16; j++) {
                sv[j] = __expf(sv[j] - Mnew);
                sum += sv[j];
            }
#pragma unroll
            for (int jj = 0; jj < 8; jj++) {
                u64 ew = *(const u64*)&Ks[base + 2 * jj];
                float e0, e1; upk2(ew, e0, e1);
                *(u64*)&Ss[base + 2 * jj] = pk2(sv[2 * jj] * e0, sv[2 * jj + 1] * e1);
            }
            sum += __shfl_xor_sync(0xffffffffu, sum, 1);
            sum += __shfl_xor_sync(0xffffffffu, sum, 2);
            if (seg == 0) {
                float scl = __expf(Mold - Mnew);
                Sc[row] = scl;
                Mrow[row] = Mnew;
                Drow[row] = Drow[row] * scl + sum;
            }
        }
        __syncthreads();

        // PV: packed over m-pairs; per 4-m chunk: 8 LDS.128 + 32 FFMA2
        {
#pragma unroll
            for (int a = 0; a < 4; a++) {
                float sc = Sc[ti + 16 * a];
                u64 sp = pk2(sc, sc);
#pragma unroll
                for (int c = 0; c < 4; c++) acc2[a][c] = mul2(acc2[a][c], sp);
            }
#pragma unroll 4
            for (int m = 0; m < TS; m += 4) {
                ulonglong2 pp[4], vv2[4];
#pragma unroll
                for (int a = 0; a < 4; a++) pp[a]  = *(const ulonglong2*)&Ss[(ti + 16 * a) * TP + m];
#pragma unroll
                for (int c = 0; c < 4; c++) vv2[c] = *(const ulonglong2*)&Vs[(c0 + c) * TP + m];
#pragma unroll
                for (int a = 0; a < 4; a++)
#pragma unroll
                    for (int c = 0; c < 4; c++) {
                        fma2(acc2[a][c], pp[a].x, vv2[c].x);
                        fma2(acc2[a][c], pp[a].y, vv2[c].y);
                    }
            }
        }
        __syncthreads();
    }

    // unpack (lo+hi = full m-sum), normalize, stage into QD area (as floats), store
    {
        float* Os = (float*)QD;        // [d][TP] float staging; QD no longer needed
#pragma unroll
        for (int a = 0; a < 4; a++) {
            float inv = 1.f / Drow[ti + 16 * a];
#pragma unroll
            for (int c = 0; c < 4; c++) {
                float lo, hi;
                upk2(acc2[a][c], lo, hi);
                Os[(c0 + c) * TP + ti + 16 * a] = (lo + hi) * inv;
            }
        }
        __syncthreads();
        float* mp = msg + (long long)b * DD * NN + (long long)h * NN;
#pragma unroll
        for (int rep = 0; rep < 4; rep++) {
            int d = tHi + rep * 16;
            *(float4*)&mp[(long long)d * hd + nBase + 4 * t4] =
                *(const float4*)&Os[d * TP + 4 * t4];
        }
    }
}

// ---------------- host ----------------
extern "C" void kernel_launch(void* const* d_in, const int* in_sizes, int n_in,
                              void* d_out, int out_size)
{
    (void)in_sizes; (void)n_in; (void)out_size;
    const float* x      = (const float*)d_in[0];
    const float* source = (const float*)d_in[1];
    const float* edge   = (const float*)d_in[2];
    const float* Wq = (const float*)d_in[3];  const float* bq = (const float*)d_in[4];
    const float* Wk = (const float*)d_in[5];  const float* bk = (const float*)d_in[6];
    const float* Wv = (const float*)d_in[7];  const float* bv = (const float*)d_in[8];
    const float* Wm = (const float*)d_in[9];  const float* bm = (const float*)d_in[10];
    const float* W1 = (const float*)d_in[11]; const float* b1 = (const float*)d_in[12];
    const float* W2 = (const float*)d_in[13]; const float* b2 = (const float*)d_in[14];
    float* out = (float*)d_out;

    float *q, *k, *v, *msg, *h2, *wfull, *bc;
    cudaGetSymbolAddress((void**)&q,     g_q);
    cudaGetSymbolAddress((void**)&k,     g_k);
    cudaGetSymbolAddress((void**)&v,     g_v);
    cudaGetSymbolAddress((void**)&msg,   g_msg);
    cudaGetSymbolAddress((void**)&h2,    g_h2);
    cudaGetSymbolAddress((void**)&wfull, g_wfull);
    cudaGetSymbolAddress((void**)&bc,    g_bc);

    dim3 blk(256);

    // --- weight folding (tiny, off the fat dependency chain)
    fold_copy_k<<<(2 * DD * DD) / 256, blk>>>(W1, wfull);
    fold_ww_k<<<dim3(DD / 128, (2 * DD) / 128), blk>>>(W1, Wm, wfull);
    fold_bias_k<<<(2 * DD) / 256, blk>>>(W1, bm, b1, bc);

    // --- fused projections: q/k/v in ONE launch (M=256, K=256, 384 CTAs)
    dim3 gqkv(NN / 128, DD / 128, 3 * BB);
    qkv_k<<<gqkv, blk>>>(Wq, Wk, Wv, bq, bk, bv, x, source, q, k, v);

    // --- fused attention (QK^T -> online softmax*edge -> PV), no prob tensor
    const int smemBytes = (2 * TS * TS + 3 * TS * TP + 3 * TS) * (int)sizeof(float);
    cudaFuncSetAttribute(flash_edge_k,
                         cudaFuncAttributeMaxDynamicSharedMemorySize, smemBytes);
    dim3 gfl(NN / TS, BB * HH);
    flash_edge_k<<<gfl, blk, smemBytes>>>(q, k, v, edge, msg);

    // --- h2 = relu(Wfull @ [x; msg] + bc)   (Wm GEMM folded away)
    dim3 gff1(NN / 128, (2 * DD) / 128, BB);
    gemm128_k<<<gff1, blk>>>(wfull, x, msg, h2, bc, 2 * DD, DD, 2 * DD, 1);

    // --- out = W2 @ h2 + b2       (M=256, K=512, single source)
    dim3 gff2(NN / 128, DD / 128, BB);
    gemm128_k<<<gff2, blk>>>(W2, h2, h2, out, b2, 2 * DD, 2 * DD, 2 * DD, 0);
}